// round 7
// baseline (speedup 1.0000x reference)
#include <cuda_runtime.h>
#include <cuda_bf16.h>
#include <math.h>
#include <stdint.h>

#define NNODES 50000
#define NEDGES 800000
#define NGRAPH 512
#define MAXF   512
#define KDIM   256

// ---- scratch (device globals; no allocation allowed) ----
__device__ float g_hs[NNODES * MAXF];       // gemm output * dis[row]
__device__ float g_x [NNODES * MAXF];       // activations after aggregate+relu
__device__ int   g_deg[NNODES];
__device__ float g_dis[NNODES];
__device__ int   g_rowstart[NNODES];
__device__ int   g_cursor[NNODES];
__device__ int   g_csr[NEDGES];
__device__ float g_wgate[NNODES];
__device__ float g_feats[NGRAPH * 1024];
__device__ int   g_tsum[1024];
__device__ int   g_gstart[NGRAPH + 1];
// bf16 split operands for tensor-core GEMMs
__device__ __nv_bfloat16 g_ahi[NNODES * KDIM];
__device__ __nv_bfloat16 g_alo[NNODES * KDIM];
__device__ __nv_bfloat16 g_wthi[512 * KDIM];   // W^T split, max 512 out-cols
__device__ __nv_bfloat16 g_wtlo[512 * KDIM];

__device__ __forceinline__ uint32_t smem_u32(const void* p) {
    uint32_t a;
    asm("{ .reg .u64 t; cvta.to.shared.u64 t, %1; cvt.u32.u64 %0, t; }"
        : "=r"(a) : "l"(p));
    return a;
}

#define LDSM4(R, addr)                                                          \
    asm volatile("ldmatrix.sync.aligned.m8n8.x4.shared.b16 {%0,%1,%2,%3}, [%4];" \
                 : "=r"((R)[0]), "=r"((R)[1]), "=r"((R)[2]), "=r"((R)[3])        \
                 : "r"(addr))

#define MMA_BF16(C, A, B0, B1)                                                  \
    asm volatile(                                                               \
        "mma.sync.aligned.m16n8k16.row.col.f32.bf16.bf16.f32 "                  \
        "{%0,%1,%2,%3}, {%4,%5,%6,%7}, {%8,%9}, {%0,%1,%2,%3};"                 \
        : "+f"((C)[0]), "+f"((C)[1]), "+f"((C)[2]), "+f"((C)[3])                \
        : "r"((A)[0]), "r"((A)[1]), "r"((A)[2]), "r"((A)[3]), "r"(B0), "r"(B1))

// ================= graph structure build =================
__global__ void k_zero() {
    for (int i = blockIdx.x * blockDim.x + threadIdx.x; i < NNODES;
         i += gridDim.x * blockDim.x) {
        g_deg[i] = 0;
        g_cursor[i] = 0;
    }
}
__global__ void k_deg(const int* __restrict__ ei) {
    for (int e = blockIdx.x * blockDim.x + threadIdx.x; e < NEDGES;
         e += gridDim.x * blockDim.x) {
        int d = ei[NEDGES + e];
        if (d >= 0 && d < NNODES) atomicAdd(&g_deg[d], 1);
    }
}
__global__ void k_dis() {
    int n = blockIdx.x * blockDim.x + threadIdx.x;
    if (n < NNODES) g_dis[n] = rsqrtf((float)(g_deg[n] + 1));
}
__global__ void k_scan1() {
    int t = blockIdx.x * blockDim.x + threadIdx.x;
    const int chunk = (NNODES + 1023) / 1024;
    int base = t * chunk, s = 0;
    for (int i = 0; i < chunk; i++) {
        int n = base + i;
        if (n < NNODES) s += g_deg[n];
    }
    g_tsum[t] = s;
}
__global__ void k_scan2() {
    __shared__ int sh[1024];
    int t = threadIdx.x;
    sh[t] = g_tsum[t];
    __syncthreads();
    for (int off = 1; off < 1024; off <<= 1) {
        int v = (t >= off) ? sh[t - off] : 0;
        __syncthreads();
        sh[t] += v;
        __syncthreads();
    }
    g_tsum[t] = (t == 0) ? 0 : sh[t - 1];
}
__global__ void k_scan3() {
    int t = blockIdx.x * blockDim.x + threadIdx.x;
    const int chunk = (NNODES + 1023) / 1024;
    int base = t * chunk, off = g_tsum[t];
    for (int i = 0; i < chunk; i++) {
        int n = base + i;
        if (n < NNODES) {
            g_rowstart[n] = off;
            off += g_deg[n];
        }
    }
}
__global__ void k_csr(const int* __restrict__ ei) {
    for (int e = blockIdx.x * blockDim.x + threadIdx.x; e < NEDGES;
         e += gridDim.x * blockDim.x) {
        int s = ei[e];
        int d = ei[NEDGES + e];
        if (s < 0 || s >= NNODES || d < 0 || d >= NNODES) continue;
        int pos = g_rowstart[d] + atomicAdd(&g_cursor[d], 1);
        if (pos >= 0 && pos < NEDGES) g_csr[pos] = s;
    }
}

// ================= fp32 -> bf16 hi/lo conversions =================
__global__ void k_cvt(const float* __restrict__ src) {
    int i = blockIdx.x * blockDim.x + threadIdx.x;
    if (i < NNODES * KDIM) {
        float x = src[i];
        __nv_bfloat16 h = __float2bfloat16(x);
        g_ahi[i] = h;
        g_alo[i] = __float2bfloat16(x - __bfloat162float(h));
    }
}
// W[K=256, Nn] -> Wt split [Nn, 256]
__global__ void k_cvtw(const float* __restrict__ W, int Nn) {
    int i = blockIdx.x * blockDim.x + threadIdx.x;
    if (i < KDIM * Nn) {
        int k = i / Nn, n = i % Nn;
        float x = W[i];
        __nv_bfloat16 h = __float2bfloat16(x);
        g_wthi[n * KDIM + k] = h;
        g_wtlo[n * KDIM + k] = __float2bfloat16(x - __bfloat162float(h));
    }
}

// ================= split-bf16 mma.sync GEMM =================
// g_hs[M, Nn] = (A @ W) * dis[row] via Ahi@Bhi + Ahi@Blo + Alo@Bhi
// A split [M, 256] in g_ahi/g_alo; W^T split [Nn, 256] in g_wthi/g_wtlo.
// CTA: 256 thr (8 warps, 4x2), tile M128 x N64, BK=32. Warp tile 32x32.
#define AP 40   // smem row stride (bf16) : 32 + 8 pad, conflict-free ldmatrix
__global__ __launch_bounds__(256, 2) void k_mmagemm(int M, int Nn) {
    __shared__ __nv_bfloat16 sm[(128 * 2 + 64 * 2) * AP];   // 30720 B
    __nv_bfloat16* sAhi = sm;                 // [128][AP]
    __nv_bfloat16* sAlo = sAhi + 128 * AP;
    __nv_bfloat16* sBhi = sAlo + 128 * AP;    // [64][AP]
    __nv_bfloat16* sBlo = sBhi + 64 * AP;

    const int tid = threadIdx.x, wid = tid >> 5, lane = tid & 31;
    const int wm = wid & 3, wn = wid >> 2;    // 4 x 2 warp grid
    const int bm = blockIdx.x * 128, nb = blockIdx.y * 64;

    const uint32_t sb = smem_u32(sm);
    const uint32_t oAlo = 128 * AP * 2;       // byte offsets
    const uint32_t oBhi = 256 * AP * 2;
    const uint32_t oBlo = oBhi + 64 * AP * 2;

    // ldmatrix per-thread source rows
    // A x4 groups: g0 rows+0..7 k0 | g1 rows+8..15 k0 | g2 rows0..7 k+8 | g3 rows8..15 k+8
    const int a_row = wm * 32 + (lane & 7) + ((lane >> 3) & 1) * 8;
    const int a_k8  = ((lane >> 4) & 1) * 8;
    // B x4 groups: g0 n0..7 k0 | g1 n0..7 k+8 | g2 n8..15 k0 | g3 n8..15 k+8
    const int b_row = wn * 32 + (lane & 7) + ((lane >> 4) & 1) * 8;
    const int b_k8  = ((lane >> 3) & 1) * 8;

    float acc[2][4][4];
#pragma unroll
    for (int mt = 0; mt < 2; mt++)
#pragma unroll
        for (int nt = 0; nt < 4; nt++)
#pragma unroll
            for (int i = 0; i < 4; i++) acc[mt][nt][i] = 0.f;

    for (int kc = 0; kc < KDIM; kc += 32) {
        // ---- load A chunk [128x32], B chunk [64x32], hi+lo ----
#pragma unroll
        for (int i = 0; i < 2; i++) {
            int idx = tid + i * 256;
            int r = idx >> 2, c8 = idx & 3;
            int grow = bm + r;
            uint4 vh = make_uint4(0, 0, 0, 0), vl = make_uint4(0, 0, 0, 0);
            if (grow < M) {
                size_t off = (size_t)grow * KDIM + kc + c8 * 8;
                vh = *(const uint4*)&g_ahi[off];
                vl = *(const uint4*)&g_alo[off];
            }
            *(uint4*)&sAhi[r * AP + c8 * 8] = vh;
            *(uint4*)&sAlo[r * AP + c8 * 8] = vl;
        }
        {
            int r = tid >> 2, c8 = tid & 3;
            size_t off = (size_t)(nb + r) * KDIM + kc + c8 * 8;
            *(uint4*)&sBhi[r * AP + c8 * 8] = *(const uint4*)&g_wthi[off];
            *(uint4*)&sBlo[r * AP + c8 * 8] = *(const uint4*)&g_wtlo[off];
        }
        __syncthreads();

        // ---- compute: 2 k16 steps ----
#pragma unroll
        for (int ks = 0; ks < 2; ks++) {
            uint32_t ah[2][4], al[2][4], bh[2][4], bl[2][4];
#pragma unroll
            for (int mt = 0; mt < 2; mt++) {
                uint32_t ad = sb +
                    (uint32_t)(((a_row + mt * 16) * AP + ks * 16 + a_k8) * 2);
                LDSM4(ah[mt], ad);
                LDSM4(al[mt], ad + oAlo);
            }
#pragma unroll
            for (int p = 0; p < 2; p++) {   // n-subtiles of 16
                uint32_t bd = sb + oBhi +
                    (uint32_t)(((b_row + p * 16) * AP + ks * 16 + b_k8) * 2);
                LDSM4(bh[p], bd);
                LDSM4(bl[p], bd + (oBlo - oBhi));
            }
#pragma unroll
            for (int mt = 0; mt < 2; mt++)
#pragma unroll
                for (int nt = 0; nt < 4; nt++) {
                    int p = nt >> 1, s2 = (nt & 1) * 2;
                    MMA_BF16(acc[mt][nt], ah[mt], bh[p][s2], bh[p][s2 + 1]);
                    MMA_BF16(acc[mt][nt], ah[mt], bl[p][s2], bl[p][s2 + 1]);
                    MMA_BF16(acc[mt][nt], al[mt], bh[p][s2], bh[p][s2 + 1]);
                }
        }
        __syncthreads();
    }

    // ---- epilogue: scale by dis[row], store fp32 ----
#pragma unroll
    for (int mt = 0; mt < 2; mt++) {
        int r0 = bm + wm * 32 + mt * 16 + (lane >> 2);
        int r1 = r0 + 8;
        float d0 = (r0 < M) ? g_dis[r0] : 0.f;
        float d1 = (r1 < M) ? g_dis[r1] : 0.f;
#pragma unroll
        for (int nt = 0; nt < 4; nt++) {
            int col = nb + wn * 32 + nt * 8 + (lane & 3) * 2;
            if (r0 < M) {
                float2 v = make_float2(acc[mt][nt][0] * d0, acc[mt][nt][1] * d0);
                *(float2*)&g_hs[(size_t)r0 * Nn + col] = v;
            }
            if (r1 < M) {
                float2 v = make_float2(acc[mt][nt][2] * d1, acc[mt][nt][3] * d1);
                *(float2*)&g_hs[(size_t)r1 * Nn + col] = v;
            }
        }
    }
}

// ---- aggregation: x[d] = relu(dis[d]*(hs[d] + sum_{s->d} hs[s]) + b)
// WB: also emit bf16 hi/lo split of the result (feeds next GEMM)
template <int F, bool WB>
__global__ void k_agg(const float* __restrict__ bias) {
    int d = blockIdx.x;
    int f = threadIdx.x;  // 256
    float dd = g_dis[d];
    float acc0 = g_hs[(size_t)d * F + f];
    float acc1 = (F == 512) ? g_hs[(size_t)d * F + f + 256] : 0.f;
    int s0 = g_rowstart[d], cnt = g_deg[d];
    for (int j = 0; j < cnt; j++) {
        int s = g_csr[s0 + j];
        acc0 += g_hs[(size_t)s * F + f];
        if (F == 512) acc1 += g_hs[(size_t)s * F + f + 256];
    }
    float v0 = fmaxf(acc0 * dd + bias[f], 0.f);
    g_x[(size_t)d * F + f] = v0;
    if (WB) {
        __nv_bfloat16 h = __float2bfloat16(v0);
        g_ahi[(size_t)d * KDIM + f] = h;
        g_alo[(size_t)d * KDIM + f] = __float2bfloat16(v0 - __bfloat162float(h));
    }
    if (F == 512)
        g_x[(size_t)d * F + f + 256] = fmaxf(acc1 * dd + bias[f + 256], 0.f);
}

// ================= pooling =================
__global__ void k_gate(const float* __restrict__ pw, const float* __restrict__ pb) {
    int warp = (blockIdx.x * blockDim.x + threadIdx.x) >> 5;
    int lane = threadIdx.x & 31;
    if (warp >= NNODES) return;
    const float* row = &g_x[(size_t)warp * 512];
    float s = 0.f;
#pragma unroll 4
    for (int i = lane; i < 512; i += 32) s += row[i] * pw[i];
#pragma unroll
    for (int o = 16; o; o >>= 1) s += __shfl_xor_sync(0xFFFFFFFFu, s, o);
    if (lane == 0) g_wgate[warp] = 1.f / (1.f + expf(-(s + pb[0])));
}

__global__ void k_gstart(const int* __restrict__ batch) {
    for (int n = blockIdx.x * blockDim.x + threadIdx.x; n < NNODES;
         n += gridDim.x * blockDim.x) {
        int b = batch[n];
        if (b < 0) b = 0;
        if (b >= NGRAPH) b = NGRAPH - 1;
        int prev = -1;
        if (n) {
            prev = batch[n - 1];
            if (prev < 0) prev = 0;
            if (prev >= NGRAPH) prev = NGRAPH - 1;
        }
        for (int g = prev + 1; g <= b; g++) g_gstart[g] = n;
        if (n == NNODES - 1)
            for (int g = b + 1; g <= NGRAPH; g++) g_gstart[g] = NNODES;
    }
}

__global__ void k_pool() {
    int g = blockIdx.x;
    int f = threadIdx.x;
    int s = g_gstart[g], e = g_gstart[g + 1];
    float ws0 = 0.f, ws1 = 0.f, mx0 = 0.f, mx1 = 0.f;
    for (int n = s; n < e; n++) {
        float w = g_wgate[n];
        float v0 = g_x[(size_t)n * 512 + f];
        float v1 = g_x[(size_t)n * 512 + f + 256];
        ws0 += v0 * w;
        ws1 += v1 * w;
        mx0 = fmaxf(mx0, v0);
        mx1 = fmaxf(mx1, v1);
    }
    g_feats[g * 1024 + f]       = ws0;
    g_feats[g * 1024 + f + 256] = ws1;
    g_feats[g * 1024 + 512 + f] = mx0;
    g_feats[g * 1024 + 768 + f] = mx1;
}

// ================= SIMT GEMM (head only) =================
template <int BM, int BN, int BK, int TM, int TN>
__global__ void k_gemm_head(const float* __restrict__ B, float* __restrict__ C,
                            int M, int Nn, int K, const float* __restrict__ bias) {
    const float* __restrict__ A = (const float*)g_feats;
    __shared__ float As[BK][BM + 4];
    __shared__ float Bs[BK][BN + 4];
    const int tid = threadIdx.x;
    const int tx = tid % (BN / TN);
    const int ty = tid / (BN / TN);
    const int bm = blockIdx.x * BM;
    const int bn = blockIdx.y * BN;

    float acc[TM][TN];
#pragma unroll
    for (int i = 0; i < TM; i++)
#pragma unroll
        for (int j = 0; j < TN; j++) acc[i][j] = 0.f;

    for (int k0 = 0; k0 < K; k0 += BK) {
#pragma unroll
        for (int i = 0; i < (BM * BK / 4) / 256; i++) {
            int idx = tid + i * 256;
            int r = idx / (BK / 4), c = idx % (BK / 4);
            int row = bm + r;
            float4 v = (row < M)
                ? *(const float4*)&A[(size_t)row * K + k0 + c * 4]
                : make_float4(0.f, 0.f, 0.f, 0.f);
            As[c * 4 + 0][r] = v.x;
            As[c * 4 + 1][r] = v.y;
            As[c * 4 + 2][r] = v.z;
            As[c * 4 + 3][r] = v.w;
        }
#pragma unroll
        for (int i = 0; i < (BK * BN / 4) / 256; i++) {
            int idx = tid + i * 256;
            int r = idx / (BN / 4), c = idx % (BN / 4);
            float4 v = *(const float4*)&B[(size_t)(k0 + r) * Nn + bn + c * 4];
            *(float4*)&Bs[r][c * 4] = v;
        }
        __syncthreads();
#pragma unroll
        for (int kk = 0; kk < BK; kk++) {
            float ra[TM], rb[TN];
#pragma unroll
            for (int i = 0; i < TM; i++) ra[i] = As[kk][ty * TM + i];
#pragma unroll
            for (int j = 0; j < TN; j++) rb[j] = Bs[kk][tx * TN + j];
#pragma unroll
            for (int i = 0; i < TM; i++)
#pragma unroll
                for (int j = 0; j < TN; j++) acc[i][j] += ra[i] * rb[j];
        }
        __syncthreads();
    }

#pragma unroll
    for (int i = 0; i < TM; i++) {
        int row = bm + ty * TM + i;
        if (row >= M) continue;
#pragma unroll
        for (int j = 0; j < TN; j++) {
            int col = bn + tx * TN + j;
            C[(size_t)row * Nn + col] = fmaxf(acc[i][j] + bias[col], 0.f);
        }
    }
}

extern "C" void kernel_launch(void* const* d_in, const int* in_sizes, int n_in,
                              void* d_out, int out_size) {
    const float* xin   = (const float*)d_in[0];
    const int*   ei    = (const int*)d_in[1];
    const int*   batch = (const int*)d_in[2];
    const float* W1 = (const float*)d_in[3];
    const float* b1 = (const float*)d_in[4];
    const float* W2 = (const float*)d_in[5];
    const float* b2 = (const float*)d_in[6];
    const float* W3 = (const float*)d_in[7];
    const float* b3 = (const float*)d_in[8];
    const float* pw = (const float*)d_in[9];
    const float* pb = (const float*)d_in[10];
    const float* Wo = (const float*)d_in[11];
    const float* bo = (const float*)d_in[12];
    float* out = (float*)d_out;

    // graph structure
    k_zero<<<196, 256>>>();
    k_deg<<<512, 256>>>(ei);
    k_dis<<<(NNODES + 255) / 256, 256>>>();
    k_scan1<<<4, 256>>>();
    k_scan2<<<1, 1024>>>();
    k_scan3<<<4, 256>>>();
    k_csr<<<512, 256>>>(ei);

    const int MBLK = (NNODES + 127) / 128;  // 391

    // layer 1
    k_cvt<<<(NNODES * KDIM + 255) / 256, 256>>>(xin);
    k_cvtw<<<(KDIM * 256 + 255) / 256, 256>>>(W1, 256);
    k_mmagemm<<<dim3(MBLK, 4), 256>>>(NNODES, 256);
    k_agg<256, true><<<NNODES, 256>>>(b1);

    // layer 2
    k_cvtw<<<(KDIM * 256 + 255) / 256, 256>>>(W2, 256);
    k_mmagemm<<<dim3(MBLK, 4), 256>>>(NNODES, 256);
    k_agg<256, true><<<NNODES, 256>>>(b2);

    // layer 3
    k_cvtw<<<(KDIM * 512 + 255) / 256, 256>>>(W3, 512);
    k_mmagemm<<<dim3(MBLK, 8), 256>>>(NNODES, 512);
    k_agg<512, false><<<NNODES, 256>>>(b3);

    // pooling
    k_gate<<<(NNODES + 7) / 8, 256>>>(pw, pb);
    k_gstart<<<196, 256>>>(batch);
    k_pool<<<NGRAPH, 256>>>();

    // head: [512,1024]@[1024,2048] + bias, relu
    k_gemm_head<64, 64, 16, 4, 4><<<dim3(8, 32), 256>>>(
        Wo, out, NGRAPH, 2048, 1024, bo);
}

// round 8
// speedup vs baseline: 1.4684x; 1.4684x over previous
#include <cuda_runtime.h>
#include <cuda_bf16.h>
#include <math.h>
#include <stdint.h>

#define NNODES 50000
#define NEDGES 800000
#define NGRAPH 512
#define MAXF   512
#define KDIM   256

// ---- scratch (device globals; no allocation allowed) ----
__device__ float g_x [NNODES * MAXF];       // activations (GEMM epilogue output)
__device__ int   g_deg[NNODES];
__device__ float g_dis[NNODES];
__device__ int   g_rowstart[NNODES];
__device__ int   g_cursor[NNODES];
__device__ int   g_csr[NEDGES];
__device__ float g_wgate[NNODES];
__device__ float g_feats[NGRAPH * 1024];
__device__ int   g_tsum[1024];
__device__ int   g_gstart[NGRAPH + 1];
// bf16 split operands for GEMMs (y = aggregated input, split hi/lo)
__device__ __nv_bfloat16 g_ahi[NNODES * KDIM];
__device__ __nv_bfloat16 g_alo[NNODES * KDIM];
__device__ __nv_bfloat16 g_wthi[512 * KDIM];   // W^T split, max 512 out-cols
__device__ __nv_bfloat16 g_wtlo[512 * KDIM];

__device__ __forceinline__ uint32_t smem_u32(const void* p) {
    uint32_t a;
    asm("{ .reg .u64 t; cvta.to.shared.u64 t, %1; cvt.u32.u64 %0, t; }"
        : "=r"(a) : "l"(p));
    return a;
}

#define LDSM4(R, addr)                                                          \
    asm volatile("ldmatrix.sync.aligned.m8n8.x4.shared.b16 {%0,%1,%2,%3}, [%4];" \
                 : "=r"((R)[0]), "=r"((R)[1]), "=r"((R)[2]), "=r"((R)[3])        \
                 : "r"(addr))

#define MMA_BF16(C, A, B0, B1)                                                  \
    asm volatile(                                                               \
        "mma.sync.aligned.m16n8k16.row.col.f32.bf16.bf16.f32 "                  \
        "{%0,%1,%2,%3}, {%4,%5,%6,%7}, {%8,%9}, {%0,%1,%2,%3};"                 \
        : "+f"((C)[0]), "+f"((C)[1]), "+f"((C)[2]), "+f"((C)[3])                \
        : "r"((A)[0]), "r"((A)[1]), "r"((A)[2]), "r"((A)[3]), "r"(B0), "r"(B1))

// ================= graph structure build =================
__global__ void k_zero() {
    for (int i = blockIdx.x * blockDim.x + threadIdx.x; i < NNODES;
         i += gridDim.x * blockDim.x) {
        g_deg[i] = 0;
        g_cursor[i] = 0;
    }
}
__global__ void k_deg(const int* __restrict__ ei) {
    for (int e = blockIdx.x * blockDim.x + threadIdx.x; e < NEDGES;
         e += gridDim.x * blockDim.x) {
        int d = ei[NEDGES + e];
        if (d >= 0 && d < NNODES) atomicAdd(&g_deg[d], 1);
    }
}
__global__ void k_dis() {
    int n = blockIdx.x * blockDim.x + threadIdx.x;
    if (n < NNODES) g_dis[n] = rsqrtf((float)(g_deg[n] + 1));
}
__global__ void k_scan1() {
    int t = blockIdx.x * blockDim.x + threadIdx.x;
    const int chunk = (NNODES + 1023) / 1024;
    int base = t * chunk, s = 0;
    for (int i = 0; i < chunk; i++) {
        int n = base + i;
        if (n < NNODES) s += g_deg[n];
    }
    g_tsum[t] = s;
}
__global__ void k_scan2() {
    __shared__ int sh[1024];
    int t = threadIdx.x;
    sh[t] = g_tsum[t];
    __syncthreads();
    for (int off = 1; off < 1024; off <<= 1) {
        int v = (t >= off) ? sh[t - off] : 0;
        __syncthreads();
        sh[t] += v;
        __syncthreads();
    }
    g_tsum[t] = (t == 0) ? 0 : sh[t - 1];
}
__global__ void k_scan3() {
    int t = blockIdx.x * blockDim.x + threadIdx.x;
    const int chunk = (NNODES + 1023) / 1024;
    int base = t * chunk, off = g_tsum[t];
    for (int i = 0; i < chunk; i++) {
        int n = base + i;
        if (n < NNODES) {
            g_rowstart[n] = off;
            off += g_deg[n];
        }
    }
}
__global__ void k_csr(const int* __restrict__ ei) {
    for (int e = blockIdx.x * blockDim.x + threadIdx.x; e < NEDGES;
         e += gridDim.x * blockDim.x) {
        int s = ei[e];
        int d = ei[NEDGES + e];
        if (s < 0 || s >= NNODES || d < 0 || d >= NNODES) continue;
        int pos = g_rowstart[d] + atomicAdd(&g_cursor[d], 1);
        if (pos >= 0 && pos < NEDGES) g_csr[pos] = s;
    }
}

// W[K=256, Nn] -> W^T split [Nn, 256]
__global__ void k_cvtw(const float* __restrict__ W, int Nn) {
    int i = blockIdx.x * blockDim.x + threadIdx.x;
    if (i < KDIM * Nn) {
        int k = i / Nn, n = i % Nn;
        float x = W[i];
        __nv_bfloat16 h = __float2bfloat16(x);
        g_wthi[n * KDIM + k] = h;
        g_wtlo[n * KDIM + k] = __float2bfloat16(x - __bfloat162float(h));
    }
}

// ---- pre-aggregation: y[d] = dis[d] * sum_{s in N(d)+{d}} x[s]*dis[s]
// Writes ONLY the bf16 hi/lo split of y (the GEMM operand).
// ASEL 0: x = ext arg (layer-1 input); ASEL 1: x = g_x
template <int ASEL>
__global__ void k_aggpre(const float* __restrict__ xext) {
    const float* __restrict__ x = (ASEL == 0) ? xext : (const float*)g_x;
    int d = blockIdx.x;
    int f = threadIdx.x;  // 256
    float dd = g_dis[d];
    float acc = x[(size_t)d * KDIM + f] * dd;
    int s0 = g_rowstart[d], cnt = g_deg[d];
    for (int j = 0; j < cnt; j++) {
        int s = g_csr[s0 + j];
        acc += x[(size_t)s * KDIM + f] * g_dis[s];
    }
    float y = acc * dd;
    __nv_bfloat16 h = __float2bfloat16(y);
    g_ahi[(size_t)d * KDIM + f] = h;
    g_alo[(size_t)d * KDIM + f] = __float2bfloat16(y - __bfloat162float(h));
}

// ================= split-bf16 mma.sync GEMM =================
// g_x[M, Nn] = relu( (Y @ W) + bias ) via Yhi@Whi + Yhi@Wlo + Ylo@Whi
// Y split [M, 256] in g_ahi/g_alo; W^T split [Nn, 256] in g_wthi/g_wtlo.
// CTA: 256 thr (8 warps, 4x2), tile M128 x N64, BK=32. Warp tile 32x32.
#define AP 40   // smem row stride (bf16): 32 + 8 pad, conflict-free ldmatrix
__global__ __launch_bounds__(256, 2) void k_mmagemm(int M, int Nn,
                                                    const float* __restrict__ bias) {
    __shared__ __nv_bfloat16 sm[(128 * 2 + 64 * 2) * AP];   // 30720 B
    __nv_bfloat16* sAhi = sm;                 // [128][AP]
    __nv_bfloat16* sAlo = sAhi + 128 * AP;
    __nv_bfloat16* sBhi = sAlo + 128 * AP;    // [64][AP]
    __nv_bfloat16* sBlo = sBhi + 64 * AP;

    const int tid = threadIdx.x, wid = tid >> 5, lane = tid & 31;
    const int wm = wid & 3, wn = wid >> 2;    // 4 x 2 warp grid
    const int bm = blockIdx.x * 128, nb = blockIdx.y * 64;

    const uint32_t sb = smem_u32(sm);
    const uint32_t oAlo = 128 * AP * 2;       // byte offsets
    const uint32_t oBhi = 256 * AP * 2;
    const uint32_t oBlo = oBhi + 64 * AP * 2;

    const int a_row = wm * 32 + (lane & 7) + ((lane >> 3) & 1) * 8;
    const int a_k8  = ((lane >> 4) & 1) * 8;
    const int b_row = wn * 32 + (lane & 7) + ((lane >> 4) & 1) * 8;
    const int b_k8  = ((lane >> 3) & 1) * 8;

    float acc[2][4][4];
#pragma unroll
    for (int mt = 0; mt < 2; mt++)
#pragma unroll
        for (int nt = 0; nt < 4; nt++)
#pragma unroll
            for (int i = 0; i < 4; i++) acc[mt][nt][i] = 0.f;

    for (int kc = 0; kc < KDIM; kc += 32) {
        // ---- load A chunk [128x32], B chunk [64x32], hi+lo ----
#pragma unroll
        for (int i = 0; i < 2; i++) {
            int idx = tid + i * 256;
            int r = idx >> 2, c8 = idx & 3;
            int grow = bm + r;
            uint4 vh = make_uint4(0, 0, 0, 0), vl = make_uint4(0, 0, 0, 0);
            if (grow < M) {
                size_t off = (size_t)grow * KDIM + kc + c8 * 8;
                vh = *(const uint4*)&g_ahi[off];
                vl = *(const uint4*)&g_alo[off];
            }
            *(uint4*)&sAhi[r * AP + c8 * 8] = vh;
            *(uint4*)&sAlo[r * AP + c8 * 8] = vl;
        }
        {
            int r = tid >> 2, c8 = tid & 3;
            size_t off = (size_t)(nb + r) * KDIM + kc + c8 * 8;
            *(uint4*)&sBhi[r * AP + c8 * 8] = *(const uint4*)&g_wthi[off];
            *(uint4*)&sBlo[r * AP + c8 * 8] = *(const uint4*)&g_wtlo[off];
        }
        __syncthreads();

#pragma unroll
        for (int ks = 0; ks < 2; ks++) {
            uint32_t ah[2][4], al[2][4], bh[2][4], bl[2][4];
#pragma unroll
            for (int mt = 0; mt < 2; mt++) {
                uint32_t ad = sb +
                    (uint32_t)(((a_row + mt * 16) * AP + ks * 16 + a_k8) * 2);
                LDSM4(ah[mt], ad);
                LDSM4(al[mt], ad + oAlo);
            }
#pragma unroll
            for (int p = 0; p < 2; p++) {
                uint32_t bd = sb + oBhi +
                    (uint32_t)(((b_row + p * 16) * AP + ks * 16 + b_k8) * 2);
                LDSM4(bh[p], bd);
                LDSM4(bl[p], bd + (oBlo - oBhi));
            }
#pragma unroll
            for (int mt = 0; mt < 2; mt++)
#pragma unroll
                for (int nt = 0; nt < 4; nt++) {
                    int p = nt >> 1, s2 = (nt & 1) * 2;
                    MMA_BF16(acc[mt][nt], ah[mt], bh[p][s2], bh[p][s2 + 1]);
                    MMA_BF16(acc[mt][nt], ah[mt], bl[p][s2], bl[p][s2 + 1]);
                    MMA_BF16(acc[mt][nt], al[mt], bh[p][s2], bh[p][s2 + 1]);
                }
        }
        __syncthreads();
    }

    // ---- epilogue: + bias, relu, store fp32 activations ----
#pragma unroll
    for (int mt = 0; mt < 2; mt++) {
        int r0 = bm + wm * 32 + mt * 16 + (lane >> 2);
        int r1 = r0 + 8;
#pragma unroll
        for (int nt = 0; nt < 4; nt++) {
            int col = nb + wn * 32 + nt * 8 + (lane & 3) * 2;
            float bb0 = bias[col], bb1 = bias[col + 1];
            if (r0 < M) {
                float2 v = make_float2(fmaxf(acc[mt][nt][0] + bb0, 0.f),
                                       fmaxf(acc[mt][nt][1] + bb1, 0.f));
                *(float2*)&g_x[(size_t)r0 * Nn + col] = v;
            }
            if (r1 < M) {
                float2 v = make_float2(fmaxf(acc[mt][nt][2] + bb0, 0.f),
                                       fmaxf(acc[mt][nt][3] + bb1, 0.f));
                *(float2*)&g_x[(size_t)r1 * Nn + col] = v;
            }
        }
    }
}

// ================= pooling =================
__global__ void k_gate(const float* __restrict__ pw, const float* __restrict__ pb) {
    int warp = (blockIdx.x * blockDim.x + threadIdx.x) >> 5;
    int lane = threadIdx.x & 31;
    if (warp >= NNODES) return;
    const float* row = &g_x[(size_t)warp * 512];
    float s = 0.f;
#pragma unroll 4
    for (int i = lane; i < 512; i += 32) s += row[i] * pw[i];
#pragma unroll
    for (int o = 16; o; o >>= 1) s += __shfl_xor_sync(0xFFFFFFFFu, s, o);
    if (lane == 0) g_wgate[warp] = 1.f / (1.f + expf(-(s + pb[0])));
}

__global__ void k_gstart(const int* __restrict__ batch) {
    for (int n = blockIdx.x * blockDim.x + threadIdx.x; n < NNODES;
         n += gridDim.x * blockDim.x) {
        int b = batch[n];
        if (b < 0) b = 0;
        if (b >= NGRAPH) b = NGRAPH - 1;
        int prev = -1;
        if (n) {
            prev = batch[n - 1];
            if (prev < 0) prev = 0;
            if (prev >= NGRAPH) prev = NGRAPH - 1;
        }
        for (int g = prev + 1; g <= b; g++) g_gstart[g] = n;
        if (n == NNODES - 1)
            for (int g = b + 1; g <= NGRAPH; g++) g_gstart[g] = NNODES;
    }
}

__global__ void k_pool() {
    int g = blockIdx.x;
    int f = threadIdx.x;
    int s = g_gstart[g], e = g_gstart[g + 1];
    float ws0 = 0.f, ws1 = 0.f, mx0 = 0.f, mx1 = 0.f;
    for (int n = s; n < e; n++) {
        float w = g_wgate[n];
        float v0 = g_x[(size_t)n * 512 + f];
        float v1 = g_x[(size_t)n * 512 + f + 256];
        ws0 += v0 * w;
        ws1 += v1 * w;
        mx0 = fmaxf(mx0, v0);
        mx1 = fmaxf(mx1, v1);
    }
    g_feats[g * 1024 + f]       = ws0;
    g_feats[g * 1024 + f + 256] = ws1;
    g_feats[g * 1024 + 512 + f] = mx0;
    g_feats[g * 1024 + 768 + f] = mx1;
}

// ================= SIMT GEMM (head only) =================
template <int BM, int BN, int BK, int TM, int TN>
__global__ void k_gemm_head(const float* __restrict__ B, float* __restrict__ C,
                            int M, int Nn, int K, const float* __restrict__ bias) {
    const float* __restrict__ A = (const float*)g_feats;
    __shared__ float As[BK][BM + 4];
    __shared__ float Bs[BK][BN + 4];
    const int tid = threadIdx.x;
    const int tx = tid % (BN / TN);
    const int ty = tid / (BN / TN);
    const int bm = blockIdx.x * BM;
    const int bn = blockIdx.y * BN;

    float acc[TM][TN];
#pragma unroll
    for (int i = 0; i < TM; i++)
#pragma unroll
        for (int j = 0; j < TN; j++) acc[i][j] = 0.f;

    for (int k0 = 0; k0 < K; k0 += BK) {
#pragma unroll
        for (int i = 0; i < (BM * BK / 4) / 256; i++) {
            int idx = tid + i * 256;
            int r = idx / (BK / 4), c = idx % (BK / 4);
            int row = bm + r;
            float4 v = (row < M)
                ? *(const float4*)&A[(size_t)row * K + k0 + c * 4]
                : make_float4(0.f, 0.f, 0.f, 0.f);
            As[c * 4 + 0][r] = v.x;
            As[c * 4 + 1][r] = v.y;
            As[c * 4 + 2][r] = v.z;
            As[c * 4 + 3][r] = v.w;
        }
#pragma unroll
        for (int i = 0; i < (BK * BN / 4) / 256; i++) {
            int idx = tid + i * 256;
            int r = idx / (BN / 4), c = idx % (BN / 4);
            float4 v = *(const float4*)&B[(size_t)(k0 + r) * Nn + bn + c * 4];
            *(float4*)&Bs[r][c * 4] = v;
        }
        __syncthreads();
#pragma unroll
        for (int kk = 0; kk < BK; kk++) {
            float ra[TM], rb[TN];
#pragma unroll
            for (int i = 0; i < TM; i++) ra[i] = As[kk][ty * TM + i];
#pragma unroll
            for (int j = 0; j < TN; j++) rb[j] = Bs[kk][tx * TN + j];
#pragma unroll
            for (int i = 0; i < TM; i++)
#pragma unroll
                for (int j = 0; j < TN; j++) acc[i][j] += ra[i] * rb[j];
        }
        __syncthreads();
    }

#pragma unroll
    for (int i = 0; i < TM; i++) {
        int row = bm + ty * TM + i;
        if (row >= M) continue;
#pragma unroll
        for (int j = 0; j < TN; j++) {
            int col = bn + tx * TN + j;
            C[(size_t)row * Nn + col] = fmaxf(acc[i][j] + bias[col], 0.f);
        }
    }
}

extern "C" void kernel_launch(void* const* d_in, const int* in_sizes, int n_in,
                              void* d_out, int out_size) {
    const float* xin   = (const float*)d_in[0];
    const int*   ei    = (const int*)d_in[1];
    const int*   batch = (const int*)d_in[2];
    const float* W1 = (const float*)d_in[3];
    const float* b1 = (const float*)d_in[4];
    const float* W2 = (const float*)d_in[5];
    const float* b2 = (const float*)d_in[6];
    const float* W3 = (const float*)d_in[7];
    const float* b3 = (const float*)d_in[8];
    const float* pw = (const float*)d_in[9];
    const float* pb = (const float*)d_in[10];
    const float* Wo = (const float*)d_in[11];
    const float* bo = (const float*)d_in[12];
    float* out = (float*)d_out;

    // graph structure
    k_zero<<<196, 256>>>();
    k_deg<<<512, 256>>>(ei);
    k_dis<<<(NNODES + 255) / 256, 256>>>();
    k_scan1<<<4, 256>>>();
    k_scan2<<<1, 1024>>>();
    k_scan3<<<4, 256>>>();
    k_csr<<<512, 256>>>(ei);

    const int MBLK = (NNODES + 127) / 128;  // 391

    // layer 1: y1 = Â xin ; x = relu(y1@W1 + b1)
    k_aggpre<0><<<NNODES, 256>>>(xin);
    k_cvtw<<<(KDIM * 256 + 255) / 256, 256>>>(W1, 256);
    k_mmagemm<<<dim3(MBLK, 4), 256>>>(NNODES, 256, b1);

    // layer 2
    k_aggpre<1><<<NNODES, 256>>>(nullptr);
    k_cvtw<<<(KDIM * 256 + 255) / 256, 256>>>(W2, 256);
    k_mmagemm<<<dim3(MBLK, 4), 256>>>(NNODES, 256, b2);

    // layer 3 (aggregation still at 256 wide!)
    k_aggpre<1><<<NNODES, 256>>>(nullptr);
    k_cvtw<<<(KDIM * 512 + 255) / 256, 256>>>(W3, 512);
    k_mmagemm<<<dim3(MBLK, 8), 256>>>(NNODES, 512, b3);

    // pooling
    k_gate<<<(NNODES + 7) / 8, 256>>>(pw, pb);
    k_gstart<<<196, 256>>>(batch);
    k_pool<<<NGRAPH, 256>>>();

    // head: [512,1024]@[1024,2048] + bias, relu
    k_gemm_head<64, 64, 16, 4, 4><<<dim3(8, 32), 256>>>(
        Wo, out, NGRAPH, 2048, 1024, bo);
}

// round 9
// speedup vs baseline: 1.6245x; 1.1064x over previous
#include <cuda_runtime.h>
#include <cuda_bf16.h>
#include <math.h>
#include <stdint.h>

#define NNODES 50000
#define NEDGES 800000
#define NGRAPH 512
#define MAXF   512
#define KDIM   256

// ---- scratch (device globals; no allocation allowed) ----
__device__ float g_x [NNODES * MAXF];       // activations (GEMM epilogue output)
__device__ int   g_deg[NNODES];
__device__ float g_dis[NNODES];
__device__ int   g_rowstart[NNODES];
__device__ int   g_cursor[NNODES];
__device__ int   g_csr[NEDGES];
__device__ float g_wgate[NNODES];
__device__ float g_feats[NGRAPH * 1024];
__device__ int   g_tsum[1024];
__device__ int   g_gstart[NGRAPH + 1];
// bf16 split operands for GEMMs (y = aggregated input, split hi/lo)
__device__ __nv_bfloat16 g_ahi[NNODES * KDIM];
__device__ __nv_bfloat16 g_alo[NNODES * KDIM];
__device__ __nv_bfloat16 g_wthi[512 * KDIM];   // W^T split, max 512 out-cols
__device__ __nv_bfloat16 g_wtlo[512 * KDIM];

__device__ __forceinline__ uint32_t smem_u32(const void* p) {
    uint32_t a;
    asm("{ .reg .u64 t; cvta.to.shared.u64 t, %1; cvt.u32.u64 %0, t; }"
        : "=r"(a) : "l"(p));
    return a;
}

#define LDSM4(R, addr)                                                          \
    asm volatile("ldmatrix.sync.aligned.m8n8.x4.shared.b16 {%0,%1,%2,%3}, [%4];" \
                 : "=r"((R)[0]), "=r"((R)[1]), "=r"((R)[2]), "=r"((R)[3])        \
                 : "r"(addr))

#define MMA_BF16(C, A, B0, B1)                                                  \
    asm volatile(                                                               \
        "mma.sync.aligned.m16n8k16.row.col.f32.bf16.bf16.f32 "                  \
        "{%0,%1,%2,%3}, {%4,%5,%6,%7}, {%8,%9}, {%0,%1,%2,%3};"                 \
        : "+f"((C)[0]), "+f"((C)[1]), "+f"((C)[2]), "+f"((C)[3])                \
        : "r"((A)[0]), "r"((A)[1]), "r"((A)[2]), "r"((A)[3]), "r"(B0), "r"(B1))

#define CP16(dst, src, sz)                                                      \
    asm volatile("cp.async.cg.shared.global [%0], [%1], 16, %2;"                \
                 :: "r"(dst), "l"(src), "r"(sz))
#define CP_COMMIT() asm volatile("cp.async.commit_group;" ::: "memory")
#define CP_WAIT(n)  asm volatile("cp.async.wait_group %0;" :: "n"(n) : "memory")

// ================= graph structure build =================
__global__ void k_zero() {
    for (int i = blockIdx.x * blockDim.x + threadIdx.x; i < NNODES;
         i += gridDim.x * blockDim.x) {
        g_deg[i] = 0;
        g_cursor[i] = 0;
    }
}
__global__ void k_deg(const int* __restrict__ ei) {
    for (int e = blockIdx.x * blockDim.x + threadIdx.x; e < NEDGES;
         e += gridDim.x * blockDim.x) {
        int d = ei[NEDGES + e];
        if (d >= 0 && d < NNODES) atomicAdd(&g_deg[d], 1);
    }
}
__global__ void k_dis() {
    int n = blockIdx.x * blockDim.x + threadIdx.x;
    if (n < NNODES) g_dis[n] = rsqrtf((float)(g_deg[n] + 1));
}
__global__ void k_scan1() {
    int t = blockIdx.x * blockDim.x + threadIdx.x;
    const int chunk = (NNODES + 1023) / 1024;
    int base = t * chunk, s = 0;
    for (int i = 0; i < chunk; i++) {
        int n = base + i;
        if (n < NNODES) s += g_deg[n];
    }
    g_tsum[t] = s;
}
__global__ void k_scan2() {
    __shared__ int sh[1024];
    int t = threadIdx.x;
    sh[t] = g_tsum[t];
    __syncthreads();
    for (int off = 1; off < 1024; off <<= 1) {
        int v = (t >= off) ? sh[t - off] : 0;
        __syncthreads();
        sh[t] += v;
        __syncthreads();
    }
    g_tsum[t] = (t == 0) ? 0 : sh[t - 1];
}
__global__ void k_scan3() {
    int t = blockIdx.x * blockDim.x + threadIdx.x;
    const int chunk = (NNODES + 1023) / 1024;
    int base = t * chunk, off = g_tsum[t];
    for (int i = 0; i < chunk; i++) {
        int n = base + i;
        if (n < NNODES) {
            g_rowstart[n] = off;
            off += g_deg[n];
        }
    }
}
__global__ void k_csr(const int* __restrict__ ei) {
    for (int e = blockIdx.x * blockDim.x + threadIdx.x; e < NEDGES;
         e += gridDim.x * blockDim.x) {
        int s = ei[e];
        int d = ei[NEDGES + e];
        if (s < 0 || s >= NNODES || d < 0 || d >= NNODES) continue;
        int pos = g_rowstart[d] + atomicAdd(&g_cursor[d], 1);
        if (pos >= 0 && pos < NEDGES) g_csr[pos] = s;
    }
}

// W[K=256, Nn] -> W^T split [Nn, 256]
__global__ void k_cvtw(const float* __restrict__ W, int Nn) {
    int i = blockIdx.x * blockDim.x + threadIdx.x;
    if (i < KDIM * Nn) {
        int k = i / Nn, n = i % Nn;
        float x = W[i];
        __nv_bfloat16 h = __float2bfloat16(x);
        g_wthi[n * KDIM + k] = h;
        g_wtlo[n * KDIM + k] = __float2bfloat16(x - __bfloat162float(h));
    }
}

// ---- pre-aggregation: y[d] = dis[d] * sum_{s in N(d)+{d}} x[s]*dis[s]
// Writes ONLY the bf16 hi/lo split of y (the GEMM operand).
template <int ASEL>
__global__ void k_aggpre(const float* __restrict__ xext) {
    const float* __restrict__ x = (ASEL == 0) ? xext : (const float*)g_x;
    int d = blockIdx.x;
    int f = threadIdx.x;  // 256
    float dd = g_dis[d];
    float acc = x[(size_t)d * KDIM + f] * dd;
    int p0 = g_rowstart[d], cnt = g_deg[d];
    int j = 0;
    for (; j + 4 <= cnt; j += 4) {   // 4 gathers in flight
        int s0 = g_csr[p0 + j],     s1 = g_csr[p0 + j + 1];
        int s2 = g_csr[p0 + j + 2], s3 = g_csr[p0 + j + 3];
        float v0 = x[(size_t)s0 * KDIM + f];
        float v1 = x[(size_t)s1 * KDIM + f];
        float v2 = x[(size_t)s2 * KDIM + f];
        float v3 = x[(size_t)s3 * KDIM + f];
        acc += v0 * g_dis[s0] + v1 * g_dis[s1] + v2 * g_dis[s2] + v3 * g_dis[s3];
    }
    for (; j < cnt; j++) {
        int s = g_csr[p0 + j];
        acc += x[(size_t)s * KDIM + f] * g_dis[s];
    }
    float y = acc * dd;
    __nv_bfloat16 h = __float2bfloat16(y);
    g_ahi[(size_t)d * KDIM + f] = h;
    g_alo[(size_t)d * KDIM + f] = __float2bfloat16(y - __bfloat162float(h));
}

// ================= split-bf16 mma.sync GEMM, cp.async 2-stage =================
// g_x[M, Nn] = relu( (Y @ W) + bias ) via Yhi@Whi + Yhi@Wlo + Ylo@Whi
// smem per stage: A rows 128x128B (hi chunks 0-3 | lo chunks 4-7), B rows 64x128B.
// SW128 swizzle: phys_chunk = chunk ^ (row & 7)  -> conflict-free ldmatrix.
#define STG_SZ 24576            // 16KB A + 8KB B
#define OB     16384            // B offset within stage
__global__ __launch_bounds__(256, 2) void k_mmagemm(int M, int Nn,
                                                    const float* __restrict__ bias) {
    __shared__ __align__(16) char sm[2 * STG_SZ];   // 49152 B
    const int tid = threadIdx.x, wid = tid >> 5, lane = tid & 31;
    const int wm = wid & 3, wn = wid >> 2;    // 4 x 2 warp grid
    const int bm = blockIdx.x * 128, nb = blockIdx.y * 64;
    const uint32_t sb = smem_u32(sm);

    // ldmatrix lane patterns (row within warp tile, 16B k-chunk index 0/1 per ks)
    const int a_row = wm * 32 + (lane & 7) + ((lane >> 3) & 1) * 8;
    const int a_c   = (lane >> 4) & 1;      // k8 chunk
    const int b_row = wn * 32 + (lane & 7) + ((lane >> 4) & 1) * 8;
    const int b_c   = (lane >> 3) & 1;

    float acc[2][4][4];
#pragma unroll
    for (int mt = 0; mt < 2; mt++)
#pragma unroll
        for (int nt = 0; nt < 4; nt++)
#pragma unroll
            for (int i = 0; i < 4; i++) acc[mt][nt][i] = 0.f;

    // ---- stage loader: chunk kc (BK=32) into stage buffer s ----
    auto load_stage = [&](int kc, int s) {
        uint32_t base = sb + s * STG_SZ;
        // A: 128 rows x 8 chunks (0-3 hi, 4-7 lo) = 1024 chunks, 4 per thread
#pragma unroll
        for (int i = 0; i < 4; i++) {
            int idx = tid + i * 256;
            int r = idx >> 3, cc = idx & 7;
            int grow = bm + r;
            int ok = (grow < M);
            int grc = ok ? grow : (M - 1);
            const __nv_bfloat16* src = (cc < 4)
                ? &g_ahi[(size_t)grc * KDIM + kc * 32 + cc * 8]
                : &g_alo[(size_t)grc * KDIM + kc * 32 + (cc - 4) * 8];
            uint32_t dst = base + (r << 7) + ((cc ^ (r & 7)) << 4);
            CP16(dst, src, ok ? 16 : 0);
        }
        // B: 64 rows x 8 chunks = 512 chunks, 2 per thread
#pragma unroll
        for (int i = 0; i < 2; i++) {
            int idx = tid + i * 256;
            int r = idx >> 3, cc = idx & 7;
            const __nv_bfloat16* src = (cc < 4)
                ? &g_wthi[(size_t)(nb + r) * KDIM + kc * 32 + cc * 8]
                : &g_wtlo[(size_t)(nb + r) * KDIM + kc * 32 + (cc - 4) * 8];
            uint32_t dst = base + OB + (r << 7) + ((cc ^ (r & 7)) << 4);
            CP16(dst, src, 16);
        }
    };

    load_stage(0, 0);
    CP_COMMIT();

    const int NKC = KDIM / 32;  // 8
    for (int kc = 0; kc < NKC; kc++) {
        int s = kc & 1;
        if (kc + 1 < NKC) {
            load_stage(kc + 1, s ^ 1);
            CP_COMMIT();
            CP_WAIT(1);
        } else {
            CP_WAIT(0);
        }
        __syncthreads();

        uint32_t stg = sb + s * STG_SZ;
#pragma unroll
        for (int ks = 0; ks < 2; ks++) {
            uint32_t ah[2][4], al[2][4], bh[2][4], bl[2][4];
            int ach = ks * 2 + a_c;
            int bch = ks * 2 + b_c;
#pragma unroll
            for (int mt = 0; mt < 2; mt++) {
                int row = a_row + mt * 16;
                uint32_t rb_ = stg + (row << 7);
                LDSM4(ah[mt], rb_ + ((ach ^ (row & 7)) << 4));
                LDSM4(al[mt], rb_ + (((ach + 4) ^ (row & 7)) << 4));
            }
#pragma unroll
            for (int p = 0; p < 2; p++) {
                int row = b_row + p * 16;
                uint32_t rb_ = stg + OB + (row << 7);
                LDSM4(bh[p], rb_ + ((bch ^ (row & 7)) << 4));
                LDSM4(bl[p], rb_ + (((bch + 4) ^ (row & 7)) << 4));
            }
#pragma unroll
            for (int mt = 0; mt < 2; mt++)
#pragma unroll
                for (int nt = 0; nt < 4; nt++) {
                    int p = nt >> 1, s2 = (nt & 1) * 2;
                    MMA_BF16(acc[mt][nt], ah[mt], bh[p][s2], bh[p][s2 + 1]);
                    MMA_BF16(acc[mt][nt], ah[mt], bl[p][s2], bl[p][s2 + 1]);
                    MMA_BF16(acc[mt][nt], al[mt], bh[p][s2], bh[p][s2 + 1]);
                }
        }
        __syncthreads();
    }

    // ---- epilogue: + bias, relu, store fp32 activations ----
#pragma unroll
    for (int mt = 0; mt < 2; mt++) {
        int r0 = bm + wm * 32 + mt * 16 + (lane >> 2);
        int r1 = r0 + 8;
#pragma unroll
        for (int nt = 0; nt < 4; nt++) {
            int col = nb + wn * 32 + nt * 8 + (lane & 3) * 2;
            float bb0 = bias[col], bb1 = bias[col + 1];
            if (r0 < M) {
                float2 v = make_float2(fmaxf(acc[mt][nt][0] + bb0, 0.f),
                                       fmaxf(acc[mt][nt][1] + bb1, 0.f));
                *(float2*)&g_x[(size_t)r0 * Nn + col] = v;
            }
            if (r1 < M) {
                float2 v = make_float2(fmaxf(acc[mt][nt][2] + bb0, 0.f),
                                       fmaxf(acc[mt][nt][3] + bb1, 0.f));
                *(float2*)&g_x[(size_t)r1 * Nn + col] = v;
            }
        }
    }
}

// ================= pooling =================
__global__ void k_gate(const float* __restrict__ pw, const float* __restrict__ pb) {
    int warp = (blockIdx.x * blockDim.x + threadIdx.x) >> 5;
    int lane = threadIdx.x & 31;
    if (warp >= NNODES) return;
    const float* row = &g_x[(size_t)warp * 512];
    float s = 0.f;
#pragma unroll 4
    for (int i = lane; i < 512; i += 32) s += row[i] * pw[i];
#pragma unroll
    for (int o = 16; o; o >>= 1) s += __shfl_xor_sync(0xFFFFFFFFu, s, o);
    if (lane == 0) g_wgate[warp] = 1.f / (1.f + expf(-(s + pb[0])));
}

__global__ void k_gstart(const int* __restrict__ batch) {
    for (int n = blockIdx.x * blockDim.x + threadIdx.x; n < NNODES;
         n += gridDim.x * blockDim.x) {
        int b = batch[n];
        if (b < 0) b = 0;
        if (b >= NGRAPH) b = NGRAPH - 1;
        int prev = -1;
        if (n) {
            prev = batch[n - 1];
            if (prev < 0) prev = 0;
            if (prev >= NGRAPH) prev = NGRAPH - 1;
        }
        for (int g = prev + 1; g <= b; g++) g_gstart[g] = n;
        if (n == NNODES - 1)
            for (int g = b + 1; g <= NGRAPH; g++) g_gstart[g] = NNODES;
    }
}

__global__ void k_pool() {
    int g = blockIdx.x;
    int f = threadIdx.x;
    int s = g_gstart[g], e = g_gstart[g + 1];
    float ws0 = 0.f, ws1 = 0.f, mx0 = 0.f, mx1 = 0.f;
    for (int n = s; n < e; n++) {
        float w = g_wgate[n];
        float v0 = g_x[(size_t)n * 512 + f];
        float v1 = g_x[(size_t)n * 512 + f + 256];
        ws0 += v0 * w;
        ws1 += v1 * w;
        mx0 = fmaxf(mx0, v0);
        mx1 = fmaxf(mx1, v1);
    }
    g_feats[g * 1024 + f]       = ws0;
    g_feats[g * 1024 + f + 256] = ws1;
    g_feats[g * 1024 + 512 + f] = mx0;
    g_feats[g * 1024 + 768 + f] = mx1;
}

// ================= SIMT GEMM (head only) =================
template <int BM, int BN, int BK, int TM, int TN>
__global__ void k_gemm_head(const float* __restrict__ B, float* __restrict__ C,
                            int M, int Nn, int K, const float* __restrict__ bias) {
    const float* __restrict__ A = (const float*)g_feats;
    __shared__ float As[BK][BM + 4];
    __shared__ float Bs[BK][BN + 4];
    const int tid = threadIdx.x;
    const int tx = tid % (BN / TN);
    const int ty = tid / (BN / TN);
    const int bm = blockIdx.x * BM;
    const int bn = blockIdx.y * BN;

    float acc[TM][TN];
#pragma unroll
    for (int i = 0; i < TM; i++)
#pragma unroll
        for (int j = 0; j < TN; j++) acc[i][j] = 0.f;

    for (int k0 = 0; k0 < K; k0 += BK) {
#pragma unroll
        for (int i = 0; i < (BM * BK / 4) / 256; i++) {
            int idx = tid + i * 256;
            int r = idx / (BK / 4), c = idx % (BK / 4);
            int row = bm + r;
            float4 v = (row < M)
                ? *(const float4*)&A[(size_t)row * K + k0 + c * 4]
                : make_float4(0.f, 0.f, 0.f, 0.f);
            As[c * 4 + 0][r] = v.x;
            As[c * 4 + 1][r] = v.y;
            As[c * 4 + 2][r] = v.z;
            As[c * 4 + 3][r] = v.w;
        }
#pragma unroll
        for (int i = 0; i < (BK * BN / 4) / 256; i++) {
            int idx = tid + i * 256;
            int r = idx / (BN / 4), c = idx % (BN / 4);
            float4 v = *(const float4*)&B[(size_t)(k0 + r) * Nn + bn + c * 4];
            *(float4*)&Bs[r][c * 4] = v;
        }
        __syncthreads();
#pragma unroll
        for (int kk = 0; kk < BK; kk++) {
            float ra[TM], rb[TN];
#pragma unroll
            for (int i = 0; i < TM; i++) ra[i] = As[kk][ty * TM + i];
#pragma unroll
            for (int j = 0; j < TN; j++) rb[j] = Bs[kk][tx * TN + j];
#pragma unroll
            for (int i = 0; i < TM; i++)
#pragma unroll
                for (int j = 0; j < TN; j++) acc[i][j] += ra[i] * rb[j];
        }
        __syncthreads();
    }

#pragma unroll
    for (int i = 0; i < TM; i++) {
        int row = bm + ty * TM + i;
        if (row >= M) continue;
#pragma unroll
        for (int j = 0; j < TN; j++) {
            int col = bn + tx * TN + j;
            C[(size_t)row * Nn + col] = fmaxf(acc[i][j] + bias[col], 0.f);
        }
    }
}

extern "C" void kernel_launch(void* const* d_in, const int* in_sizes, int n_in,
                              void* d_out, int out_size) {
    const float* xin   = (const float*)d_in[0];
    const int*   ei    = (const int*)d_in[1];
    const int*   batch = (const int*)d_in[2];
    const float* W1 = (const float*)d_in[3];
    const float* b1 = (const float*)d_in[4];
    const float* W2 = (const float*)d_in[5];
    const float* b2 = (const float*)d_in[6];
    const float* W3 = (const float*)d_in[7];
    const float* b3 = (const float*)d_in[8];
    const float* pw = (const float*)d_in[9];
    const float* pb = (const float*)d_in[10];
    const float* Wo = (const float*)d_in[11];
    const float* bo = (const float*)d_in[12];
    float* out = (float*)d_out;

    // graph structure
    k_zero<<<196, 256>>>();
    k_deg<<<512, 256>>>(ei);
    k_dis<<<(NNODES + 255) / 256, 256>>>();
    k_scan1<<<4, 256>>>();
    k_scan2<<<1, 1024>>>();
    k_scan3<<<4, 256>>>();
    k_csr<<<512, 256>>>(ei);

    const int MBLK = (NNODES + 127) / 128;  // 391

    // layer 1: y1 = Â xin ; x = relu(y1@W1 + b1)
    k_aggpre<0><<<NNODES, 256>>>(xin);
    k_cvtw<<<(KDIM * 256 + 255) / 256, 256>>>(W1, 256);
    k_mmagemm<<<dim3(MBLK, 4), 256>>>(NNODES, 256, b1);

    // layer 2
    k_aggpre<1><<<NNODES, 256>>>(nullptr);
    k_cvtw<<<(KDIM * 256 + 255) / 256, 256>>>(W2, 256);
    k_mmagemm<<<dim3(MBLK, 4), 256>>>(NNODES, 256, b2);

    // layer 3 (aggregation at 256 wide)
    k_aggpre<1><<<NNODES, 256>>>(nullptr);
    k_cvtw<<<(KDIM * 512 + 255) / 256, 256>>>(W3, 512);
    k_mmagemm<<<dim3(MBLK, 8), 256>>>(NNODES, 512, b3);

    // pooling
    k_gate<<<(NNODES + 7) / 8, 256>>>(pw, pb);
    k_gstart<<<196, 256>>>(batch);
    k_pool<<<NGRAPH, 256>>>();

    // head: [512,1024]@[1024,2048] + bias, relu
    k_gemm_head<64, 64, 16, 4, 4><<<dim3(8, 32), 256>>>(
        Wo, out, NGRAPH, 2048, 1024, bo);
}

// round 10
// speedup vs baseline: 1.7042x; 1.0490x over previous
#include <cuda_runtime.h>
#include <cuda_bf16.h>
#include <math.h>
#include <stdint.h>

#define NNODES 50000
#define NEDGES 800000
#define NGRAPH 512
#define MAXF   512
#define KDIM   256

// ---- scratch (device globals; no allocation allowed) ----
__device__ float g_x [NNODES * MAXF];       // activations (GEMM epilogue output)
__device__ int   g_deg[NNODES];
__device__ float g_dis[NNODES];
__device__ int   g_rowstart[NNODES];
__device__ int   g_cursor[NNODES];
__device__ int   g_csr[NEDGES];
__device__ float g_wgate[NNODES];
__device__ int   g_tsum[1024];
__device__ int   g_gstart[NGRAPH + 1];
// bf16 split operands for GEMMs (A operand rows; also holds pooled feats for head)
__device__ __nv_bfloat16 g_ahi[NNODES * KDIM];
__device__ __nv_bfloat16 g_alo[NNODES * KDIM];
__device__ __nv_bfloat16 g_wthi[2048 * 1024];   // W^T split (max: head 2048x1024)
__device__ __nv_bfloat16 g_wtlo[2048 * 1024];

__device__ __forceinline__ uint32_t smem_u32(const void* p) {
    uint32_t a;
    asm("{ .reg .u64 t; cvta.to.shared.u64 t, %1; cvt.u32.u64 %0, t; }"
        : "=r"(a) : "l"(p));
    return a;
}

#define LDSM4(R, addr)                                                          \
    asm volatile("ldmatrix.sync.aligned.m8n8.x4.shared.b16 {%0,%1,%2,%3}, [%4];" \
                 : "=r"((R)[0]), "=r"((R)[1]), "=r"((R)[2]), "=r"((R)[3])        \
                 : "r"(addr))

#define MMA_BF16(C, A, B0, B1)                                                  \
    asm volatile(                                                               \
        "mma.sync.aligned.m16n8k16.row.col.f32.bf16.bf16.f32 "                  \
        "{%0,%1,%2,%3}, {%4,%5,%6,%7}, {%8,%9}, {%0,%1,%2,%3};"                 \
        : "+f"((C)[0]), "+f"((C)[1]), "+f"((C)[2]), "+f"((C)[3])                \
        : "r"((A)[0]), "r"((A)[1]), "r"((A)[2]), "r"((A)[3]), "r"(B0), "r"(B1))

#define CP16(dst, src, sz)                                                      \
    asm volatile("cp.async.cg.shared.global [%0], [%1], 16, %2;"                \
                 :: "r"(dst), "l"(src), "r"(sz))
#define CP_COMMIT() asm volatile("cp.async.commit_group;" ::: "memory")
#define CP_WAIT(n)  asm volatile("cp.async.wait_group %0;" :: "n"(n) : "memory")

// ================= graph structure build =================
__global__ void k_zero() {
    for (int i = blockIdx.x * blockDim.x + threadIdx.x; i < NNODES;
         i += gridDim.x * blockDim.x) {
        g_deg[i] = 0;
        g_cursor[i] = 0;
    }
}
__global__ void k_deg(const int* __restrict__ ei) {
    for (int e = blockIdx.x * blockDim.x + threadIdx.x; e < NEDGES;
         e += gridDim.x * blockDim.x) {
        int d = ei[NEDGES + e];
        if (d >= 0 && d < NNODES) atomicAdd(&g_deg[d], 1);
    }
}
__global__ void k_dis() {
    int n = blockIdx.x * blockDim.x + threadIdx.x;
    if (n < NNODES) g_dis[n] = rsqrtf((float)(g_deg[n] + 1));
}
__global__ void k_scan1() {
    int t = blockIdx.x * blockDim.x + threadIdx.x;
    const int chunk = (NNODES + 1023) / 1024;
    int base = t * chunk, s = 0;
    for (int i = 0; i < chunk; i++) {
        int n = base + i;
        if (n < NNODES) s += g_deg[n];
    }
    g_tsum[t] = s;
}
__global__ void k_scan2() {
    __shared__ int sh[1024];
    int t = threadIdx.x;
    sh[t] = g_tsum[t];
    __syncthreads();
    for (int off = 1; off < 1024; off <<= 1) {
        int v = (t >= off) ? sh[t - off] : 0;
        __syncthreads();
        sh[t] += v;
        __syncthreads();
    }
    g_tsum[t] = (t == 0) ? 0 : sh[t - 1];
}
__global__ void k_scan3() {
    int t = blockIdx.x * blockDim.x + threadIdx.x;
    const int chunk = (NNODES + 1023) / 1024;
    int base = t * chunk, off = g_tsum[t];
    for (int i = 0; i < chunk; i++) {
        int n = base + i;
        if (n < NNODES) {
            g_rowstart[n] = off;
            off += g_deg[n];
        }
    }
}
__global__ void k_csr(const int* __restrict__ ei) {
    for (int e = blockIdx.x * blockDim.x + threadIdx.x; e < NEDGES;
         e += gridDim.x * blockDim.x) {
        int s = ei[e];
        int d = ei[NEDGES + e];
        if (s < 0 || s >= NNODES || d < 0 || d >= NNODES) continue;
        int pos = g_rowstart[d] + atomicAdd(&g_cursor[d], 1);
        if (pos >= 0 && pos < NEDGES) g_csr[pos] = s;
    }
}

// W[K, Nn] -> W^T split [Nn, K]
__global__ void k_cvtw(const float* __restrict__ W, int Nn, int K) {
    int i = blockIdx.x * blockDim.x + threadIdx.x;
    if (i < K * Nn) {
        int k = i / Nn, n = i % Nn;
        float x = W[i];
        __nv_bfloat16 h = __float2bfloat16(x);
        g_wthi[(size_t)n * K + k] = h;
        g_wtlo[(size_t)n * K + k] = __float2bfloat16(x - __bfloat162float(h));
    }
}

// ---- pre-aggregation: y[d] = dis[d] * sum_{s in N(d)+{d}} x[s]*dis[s]
template <int ASEL>
__global__ void k_aggpre(const float* __restrict__ xext) {
    const float* __restrict__ x = (ASEL == 0) ? xext : (const float*)g_x;
    int d = blockIdx.x;
    int f = threadIdx.x;  // 256
    float dd = g_dis[d];
    float acc = x[(size_t)d * KDIM + f] * dd;
    int p0 = g_rowstart[d], cnt = g_deg[d];
    int j = 0;
    for (; j + 4 <= cnt; j += 4) {
        int s0 = g_csr[p0 + j],     s1 = g_csr[p0 + j + 1];
        int s2 = g_csr[p0 + j + 2], s3 = g_csr[p0 + j + 3];
        float v0 = x[(size_t)s0 * KDIM + f];
        float v1 = x[(size_t)s1 * KDIM + f];
        float v2 = x[(size_t)s2 * KDIM + f];
        float v3 = x[(size_t)s3 * KDIM + f];
        acc += v0 * g_dis[s0] + v1 * g_dis[s1] + v2 * g_dis[s2] + v3 * g_dis[s3];
    }
    for (; j < cnt; j++) {
        int s = g_csr[p0 + j];
        acc += x[(size_t)s * KDIM + f] * g_dis[s];
    }
    float y = acc * dd;
    __nv_bfloat16 h = __float2bfloat16(y);
    g_ahi[(size_t)d * KDIM + f] = h;
    g_alo[(size_t)d * KDIM + f] = __float2bfloat16(y - __bfloat162float(h));
}

// ================= split-bf16 mma.sync GEMM, 128x128 tile, cp.async 2-stage ===
// C[M, Nn] = relu( (A @ W) + bias ),  A split [M,K] in g_ahi/g_alo,
// W^T split [Nn,K] in g_wthi/g_wtlo.  CSEL: 0 = Cout arg, 1 = g_x.
// Stage: A 128 rows x 128B (chunks 0-3 hi | 4-7 lo), B 128 rows x 128B.
// SW128 swizzle: phys chunk = chunk ^ (row & 7).
#define STG_SZ 32768
#define OB     16384
template <int CSEL>
__global__ __launch_bounds__(256, 2) void k_mmagemm(float* __restrict__ Cout,
                                                    int M, int Nn, int K,
                                                    const float* __restrict__ bias) {
    extern __shared__ __align__(16) char sm[];     // 2 * STG_SZ
    float* __restrict__ C = (CSEL == 0) ? Cout : (float*)g_x;
    const int tid = threadIdx.x, wid = tid >> 5, lane = tid & 31;
    const int wm = wid & 3, wn = wid >> 2;    // 4 x 2 warps, warp tile 32 x 64
    const int bm = blockIdx.x * 128, nb = blockIdx.y * 128;
    const uint32_t sb = smem_u32(sm);

    const int a_row = wm * 32 + (lane & 7) + ((lane >> 3) & 1) * 8;
    const int a_c   = (lane >> 4) & 1;
    const int b_row = wn * 64 + (lane & 7) + ((lane >> 4) & 1) * 8;
    const int b_c   = (lane >> 3) & 1;

    float acc[2][8][4];
#pragma unroll
    for (int mt = 0; mt < 2; mt++)
#pragma unroll
        for (int nt = 0; nt < 8; nt++)
#pragma unroll
            for (int i = 0; i < 4; i++) acc[mt][nt][i] = 0.f;

    auto load_stage = [&](int kc, int s) {
        uint32_t base = sb + s * STG_SZ;
        // A: 128 rows x 8 chunks = 1024, 4 per thread
#pragma unroll
        for (int i = 0; i < 4; i++) {
            int idx = tid + i * 256;
            int r = idx >> 3, cc = idx & 7;
            int grow = bm + r;
            int ok = (grow < M);
            int grc = ok ? grow : (M - 1);
            const __nv_bfloat16* src = (cc < 4)
                ? &g_ahi[(size_t)grc * K + kc * 32 + cc * 8]
                : &g_alo[(size_t)grc * K + kc * 32 + (cc - 4) * 8];
            uint32_t dst = base + (r << 7) + ((cc ^ (r & 7)) << 4);
            CP16(dst, src, ok ? 16 : 0);
        }
        // B: 128 rows x 8 chunks = 1024, 4 per thread
#pragma unroll
        for (int i = 0; i < 4; i++) {
            int idx = tid + i * 256;
            int r = idx >> 3, cc = idx & 7;
            const __nv_bfloat16* src = (cc < 4)
                ? &g_wthi[(size_t)(nb + r) * K + kc * 32 + cc * 8]
                : &g_wtlo[(size_t)(nb + r) * K + kc * 32 + (cc - 4) * 8];
            uint32_t dst = base + OB + (r << 7) + ((cc ^ (r & 7)) << 4);
            CP16(dst, src, 16);
        }
    };

    load_stage(0, 0);
    CP_COMMIT();

    const int NKC = K / 32;
    for (int kc = 0; kc < NKC; kc++) {
        int s = kc & 1;
        if (kc + 1 < NKC) {
            load_stage(kc + 1, s ^ 1);
            CP_COMMIT();
            CP_WAIT(1);
        } else {
            CP_WAIT(0);
        }
        __syncthreads();

        uint32_t stg = sb + s * STG_SZ;
#pragma unroll
        for (int ks = 0; ks < 2; ks++) {
            uint32_t ah[2][4], al[2][4], bh[4][4], bl[4][4];
            int ach = ks * 2 + a_c;
            int bch = ks * 2 + b_c;
#pragma unroll
            for (int mt = 0; mt < 2; mt++) {
                int row = a_row + mt * 16;
                uint32_t rb_ = stg + (row << 7);
                LDSM4(ah[mt], rb_ + ((ach ^ (row & 7)) << 4));
                LDSM4(al[mt], rb_ + (((ach + 4) ^ (row & 7)) << 4));
            }
#pragma unroll
            for (int p = 0; p < 4; p++) {
                int row = b_row + p * 16;
                uint32_t rb_ = stg + OB + (row << 7);
                LDSM4(bh[p], rb_ + ((bch ^ (row & 7)) << 4));
                LDSM4(bl[p], rb_ + (((bch + 4) ^ (row & 7)) << 4));
            }
#pragma unroll
            for (int mt = 0; mt < 2; mt++)
#pragma unroll
                for (int nt = 0; nt < 8; nt++) {
                    int p = nt >> 1, s2 = (nt & 1) * 2;
                    MMA_BF16(acc[mt][nt], ah[mt], bh[p][s2], bh[p][s2 + 1]);
                    MMA_BF16(acc[mt][nt], ah[mt], bl[p][s2], bl[p][s2 + 1]);
                    MMA_BF16(acc[mt][nt], al[mt], bh[p][s2], bh[p][s2 + 1]);
                }
        }
        __syncthreads();
    }

    // ---- epilogue: + bias, relu, store fp32 ----
#pragma unroll
    for (int mt = 0; mt < 2; mt++) {
        int r0 = bm + wm * 32 + mt * 16 + (lane >> 2);
        int r1 = r0 + 8;
#pragma unroll
        for (int nt = 0; nt < 8; nt++) {
            int col = nb + wn * 64 + nt * 8 + (lane & 3) * 2;
            float bb0 = bias[col], bb1 = bias[col + 1];
            if (r0 < M) {
                float2 v = make_float2(fmaxf(acc[mt][nt][0] + bb0, 0.f),
                                       fmaxf(acc[mt][nt][1] + bb1, 0.f));
                *(float2*)&C[(size_t)r0 * Nn + col] = v;
            }
            if (r1 < M) {
                float2 v = make_float2(fmaxf(acc[mt][nt][2] + bb0, 0.f),
                                       fmaxf(acc[mt][nt][3] + bb1, 0.f));
                *(float2*)&C[(size_t)r1 * Nn + col] = v;
            }
        }
    }
}

// ================= pooling =================
__global__ void k_gate(const float* __restrict__ pw, const float* __restrict__ pb) {
    int warp = (blockIdx.x * blockDim.x + threadIdx.x) >> 5;
    int lane = threadIdx.x & 31;
    if (warp >= NNODES) return;
    const float* row = &g_x[(size_t)warp * 512];
    float s = 0.f;
#pragma unroll 4
    for (int i = lane; i < 512; i += 32) s += row[i] * pw[i];
#pragma unroll
    for (int o = 16; o; o >>= 1) s += __shfl_xor_sync(0xFFFFFFFFu, s, o);
    if (lane == 0) g_wgate[warp] = 1.f / (1.f + expf(-(s + pb[0])));
}

__global__ void k_gstart(const int* __restrict__ batch) {
    for (int n = blockIdx.x * blockDim.x + threadIdx.x; n < NNODES;
         n += gridDim.x * blockDim.x) {
        int b = batch[n];
        if (b < 0) b = 0;
        if (b >= NGRAPH) b = NGRAPH - 1;
        int prev = -1;
        if (n) {
            prev = batch[n - 1];
            if (prev < 0) prev = 0;
            if (prev >= NGRAPH) prev = NGRAPH - 1;
        }
        for (int g = prev + 1; g <= b; g++) g_gstart[g] = n;
        if (n == NNODES - 1)
            for (int g = b + 1; g <= NGRAPH; g++) g_gstart[g] = NNODES;
    }
}

// pool writes the head GEMM A operand (bf16 hi/lo split, row g, K=1024)
__global__ void k_pool() {
    int g = blockIdx.x;
    int f = threadIdx.x;  // 256
    int s = g_gstart[g], e = g_gstart[g + 1];
    float ws0 = 0.f, ws1 = 0.f, mx0 = 0.f, mx1 = 0.f;
    for (int n = s; n < e; n++) {
        float w = g_wgate[n];
        float v0 = g_x[(size_t)n * 512 + f];
        float v1 = g_x[(size_t)n * 512 + f + 256];
        ws0 += v0 * w;
        ws1 += v1 * w;
        mx0 = fmaxf(mx0, v0);
        mx1 = fmaxf(mx1, v1);
    }
    size_t base = (size_t)g * 1024;
    float vs[4] = {ws0, ws1, mx0, mx1};
    int   cs[4] = {f, f + 256, 512 + f, 768 + f};
#pragma unroll
    for (int i = 0; i < 4; i++) {
        __nv_bfloat16 h = __float2bfloat16(vs[i]);
        g_ahi[base + cs[i]] = h;
        g_alo[base + cs[i]] = __float2bfloat16(vs[i] - __bfloat162float(h));
    }
}

extern "C" void kernel_launch(void* const* d_in, const int* in_sizes, int n_in,
                              void* d_out, int out_size) {
    const float* xin   = (const float*)d_in[0];
    const int*   ei    = (const int*)d_in[1];
    const int*   batch = (const int*)d_in[2];
    const float* W1 = (const float*)d_in[3];
    const float* b1 = (const float*)d_in[4];
    const float* W2 = (const float*)d_in[5];
    const float* b2 = (const float*)d_in[6];
    const float* W3 = (const float*)d_in[7];
    const float* b3 = (const float*)d_in[8];
    const float* pw = (const float*)d_in[9];
    const float* pb = (const float*)d_in[10];
    const float* Wo = (const float*)d_in[11];
    const float* bo = (const float*)d_in[12];
    float* out = (float*)d_out;

    cudaFuncSetAttribute(k_mmagemm<0>, cudaFuncAttributeMaxDynamicSharedMemorySize,
                         2 * STG_SZ);
    cudaFuncSetAttribute(k_mmagemm<1>, cudaFuncAttributeMaxDynamicSharedMemorySize,
                         2 * STG_SZ);

    // graph structure
    k_zero<<<196, 256>>>();
    k_deg<<<512, 256>>>(ei);
    k_dis<<<(NNODES + 255) / 256, 256>>>();
    k_scan1<<<4, 256>>>();
    k_scan2<<<1, 1024>>>();
    k_scan3<<<4, 256>>>();
    k_csr<<<512, 256>>>(ei);

    const int MBLK = (NNODES + 127) / 128;  // 391

    // layer 1
    k_aggpre<0><<<NNODES, 256>>>(xin);
    k_cvtw<<<(KDIM * 256 + 255) / 256, 256>>>(W1, 256, KDIM);
    k_mmagemm<1><<<dim3(MBLK, 2), 256, 2 * STG_SZ>>>(nullptr, NNODES, 256, KDIM, b1);

    // layer 2
    k_aggpre<1><<<NNODES, 256>>>(nullptr);
    k_cvtw<<<(KDIM * 256 + 255) / 256, 256>>>(W2, 256, KDIM);
    k_mmagemm<1><<<dim3(MBLK, 2), 256, 2 * STG_SZ>>>(nullptr, NNODES, 256, KDIM, b2);

    // layer 3
    k_aggpre<1><<<NNODES, 256>>>(nullptr);
    k_cvtw<<<(KDIM * 512 + 255) / 256, 256>>>(W3, 512, KDIM);
    k_mmagemm<1><<<dim3(MBLK, 4), 256, 2 * STG_SZ>>>(nullptr, NNODES, 512, KDIM, b3);

    // pooling (k_pool emits head A operand split)
    k_gate<<<(NNODES + 7) / 8, 256>>>(pw, pb);
    k_gstart<<<196, 256>>>(batch);
    k_pool<<<NGRAPH, 256>>>();

    // head: [512,1024] @ [1024,2048] + bias, relu -> out
    k_cvtw<<<(1024 * 2048 + 255) / 256, 256>>>(Wo, 2048, 1024);
    k_mmagemm<0><<<dim3(4, 16), 256, 2 * STG_SZ>>>(out, NGRAPH, 2048, 1024, bo);
}

// round 12
// speedup vs baseline: 1.7813x; 1.0452x over previous
#include <cuda_runtime.h>
#include <cuda_bf16.h>
#include <math.h>
#include <stdint.h>

#define NNODES 50000
#define NEDGES 800000
#define NGRAPH 512
#define MAXF   512
#define KDIM   256

// ---- scratch (device globals; no allocation allowed) ----
__device__ float g_x [NNODES * MAXF];       // activations (GEMM epilogue output)
__device__ int   g_deg[NNODES];
__device__ float g_dis[NNODES];
__device__ int   g_rowstart[NNODES];
__device__ int   g_cursor[NNODES];
__device__ int   g_csr[NEDGES];
__device__ float g_wgate[NNODES];
__device__ int   g_tsum[1024];
__device__ int   g_gstart[NGRAPH + 1];
// bf16 split operands for GEMMs (A operand rows; also holds pooled feats for head)
__device__ __nv_bfloat16 g_ahi[NNODES * KDIM];
__device__ __nv_bfloat16 g_alo[NNODES * KDIM];
__device__ __nv_bfloat16 g_wthi[2048 * 1024];   // W^T split (max: head 2048x1024)
__device__ __nv_bfloat16 g_wtlo[2048 * 1024];

__device__ __forceinline__ uint32_t smem_u32(const void* p) {
    uint32_t a;
    asm("{ .reg .u64 t; cvta.to.shared.u64 t, %1; cvt.u32.u64 %0, t; }"
        : "=r"(a) : "l"(p));
    return a;
}

#define LDSM4(R, addr)                                                          \
    asm volatile("ldmatrix.sync.aligned.m8n8.x4.shared.b16 {%0,%1,%2,%3}, [%4];" \
                 : "=r"((R)[0]), "=r"((R)[1]), "=r"((R)[2]), "=r"((R)[3])        \
                 : "r"(addr))

#define MMA_BF16(C, A, B0, B1)                                                  \
    asm volatile(                                                               \
        "mma.sync.aligned.m16n8k16.row.col.f32.bf16.bf16.f32 "                  \
        "{%0,%1,%2,%3}, {%4,%5,%6,%7}, {%8,%9}, {%0,%1,%2,%3};"                 \
        : "+f"((C)[0]), "+f"((C)[1]), "+f"((C)[2]), "+f"((C)[3])                \
        : "r"((A)[0]), "r"((A)[1]), "r"((A)[2]), "r"((A)[3]), "r"(B0), "r"(B1))

#define CP16(dst, src, sz)                                                      \
    asm volatile("cp.async.cg.shared.global [%0], [%1], 16, %2;"                \
                 :: "r"(dst), "l"(src), "r"(sz))
#define CP_COMMIT() asm volatile("cp.async.commit_group;" ::: "memory")
#define CP_WAIT(n)  asm volatile("cp.async.wait_group %0;" :: "n"(n) : "memory")

// ================= graph structure build =================
__global__ void k_zero() {
    for (int i = blockIdx.x * blockDim.x + threadIdx.x; i < NNODES;
         i += gridDim.x * blockDim.x) {
        g_deg[i] = 0;
        g_cursor[i] = 0;
    }
}
__global__ void k_deg(const int* __restrict__ ei) {
    for (int e = blockIdx.x * blockDim.x + threadIdx.x; e < NEDGES;
         e += gridDim.x * blockDim.x) {
        int d = ei[NEDGES + e];
        if (d >= 0 && d < NNODES) atomicAdd(&g_deg[d], 1);
    }
}
__global__ void k_dis() {
    int n = blockIdx.x * blockDim.x + threadIdx.x;
    if (n < NNODES) g_dis[n] = rsqrtf((float)(g_deg[n] + 1));
}
__global__ void k_scan1() {
    int t = blockIdx.x * blockDim.x + threadIdx.x;
    const int chunk = (NNODES + 1023) / 1024;
    int base = t * chunk, s = 0;
    for (int i = 0; i < chunk; i++) {
        int n = base + i;
        if (n < NNODES) s += g_deg[n];
    }
    g_tsum[t] = s;
}
__global__ void k_scan2() {
    __shared__ int sh[1024];
    int t = threadIdx.x;
    sh[t] = g_tsum[t];
    __syncthreads();
    for (int off = 1; off < 1024; off <<= 1) {
        int v = (t >= off) ? sh[t - off] : 0;
        __syncthreads();
        sh[t] += v;
        __syncthreads();
    }
    g_tsum[t] = (t == 0) ? 0 : sh[t - 1];
}
__global__ void k_scan3() {
    int t = blockIdx.x * blockDim.x + threadIdx.x;
    const int chunk = (NNODES + 1023) / 1024;
    int base = t * chunk, off = g_tsum[t];
    for (int i = 0; i < chunk; i++) {
        int n = base + i;
        if (n < NNODES) {
            g_rowstart[n] = off;
            off += g_deg[n];
        }
    }
}
__global__ void k_csr(const int* __restrict__ ei) {
    for (int e = blockIdx.x * blockDim.x + threadIdx.x; e < NEDGES;
         e += gridDim.x * blockDim.x) {
        int s = ei[e];
        int d = ei[NEDGES + e];
        if (s < 0 || s >= NNODES || d < 0 || d >= NNODES) continue;
        int pos = g_rowstart[d] + atomicAdd(&g_cursor[d], 1);
        if (pos >= 0 && pos < NEDGES) g_csr[pos] = s;
    }
}

// ---- W[K, Nn] (row-major) -> W^T split [Nn, K], smem-tiled transpose ----
// grid: (Nn/64, K/64), block 256. K, Nn multiples of 64.
__global__ void k_cvtwT(const float* __restrict__ W, int Nn, int K) {
    __shared__ float ts[64][65];
    const int tid = threadIdx.x;
    const int n0 = blockIdx.x * 64, k0 = blockIdx.y * 64;
    // coalesced read: 64 k-rows x 64 n-cols
#pragma unroll
    for (int i = 0; i < 16; i++) {
        int idx = tid + i * 256;
        int r = idx >> 6, c = idx & 63;          // r = k offset, c = n offset
        ts[r][c] = W[(size_t)(k0 + r) * Nn + n0 + c];
    }
    __syncthreads();
    // coalesced write: 64 n-rows x 64 k-cols, packed bf16x2
#pragma unroll
    for (int i = 0; i < 8; i++) {
        int idx = tid + i * 256;                 // 2048 pairs
        int r = idx >> 5, c2 = (idx & 31) * 2;   // r = n offset, c2 = k offset
        float x0 = ts[c2][r], x1 = ts[c2 + 1][r];
        __nv_bfloat16 h0 = __float2bfloat16(x0);
        __nv_bfloat16 h1 = __float2bfloat16(x1);
        __nv_bfloat16 l0 = __float2bfloat16(x0 - __bfloat162float(h0));
        __nv_bfloat16 l1 = __float2bfloat16(x1 - __bfloat162float(h1));
        size_t off = (size_t)(n0 + r) * K + k0 + c2;
        uint32_t ph, pl;
        {
            uint16_t a0 = *(uint16_t*)&h0, a1 = *(uint16_t*)&h1;
            uint16_t b0 = *(uint16_t*)&l0, b1 = *(uint16_t*)&l1;
            ph = (uint32_t)a0 | ((uint32_t)a1 << 16);
            pl = (uint32_t)b0 | ((uint32_t)b1 << 16);
        }
        *(uint32_t*)&g_wthi[off] = ph;
        *(uint32_t*)&g_wtlo[off] = pl;
    }
}

// ---- pre-aggregation: y[d] = dis[d] * sum_{s in N(d)+{d}} x[s]*dis[s]
template <int ASEL>
__global__ void k_aggpre(const float* __restrict__ xext) {
    const float* __restrict__ x = (ASEL == 0) ? xext : (const float*)g_x;
    int d = blockIdx.x;
    int f = threadIdx.x;  // 256
    float dd = g_dis[d];
    float acc = x[(size_t)d * KDIM + f] * dd;
    int p0 = g_rowstart[d], cnt = g_deg[d];
    int j = 0;
    for (; j + 4 <= cnt; j += 4) {
        int s0 = g_csr[p0 + j],     s1 = g_csr[p0 + j + 1];
        int s2 = g_csr[p0 + j + 2], s3 = g_csr[p0 + j + 3];
        float v0 = x[(size_t)s0 * KDIM + f];
        float v1 = x[(size_t)s1 * KDIM + f];
        float v2 = x[(size_t)s2 * KDIM + f];
        float v3 = x[(size_t)s3 * KDIM + f];
        acc += v0 * g_dis[s0] + v1 * g_dis[s1] + v2 * g_dis[s2] + v3 * g_dis[s3];
    }
    for (; j < cnt; j++) {
        int s = g_csr[p0 + j];
        acc += x[(size_t)s * KDIM + f] * g_dis[s];
    }
    float y = acc * dd;
    __nv_bfloat16 h = __float2bfloat16(y);
    g_ahi[(size_t)d * KDIM + f] = h;
    g_alo[(size_t)d * KDIM + f] = __float2bfloat16(y - __bfloat162float(h));
}

// ================= split-bf16 mma.sync GEMM, 128x128 tile, cp.async 2-stage ===
// C[M, Nn] = relu( (A @ W) + bias ),  A split [M,K] in g_ahi/g_alo,
// W^T split [Nn,K] in g_wthi/g_wtlo.  CSEL: 0 = Cout arg, 1 = g_x.
#define STG_SZ 32768
#define OB     16384
template <int CSEL>
__global__ __launch_bounds__(256, 2) void k_mmagemm(float* __restrict__ Cout,
                                                    int M, int Nn, int K,
                                                    const float* __restrict__ bias) {
    extern __shared__ __align__(16) char sm[];     // 2 * STG_SZ
    float* __restrict__ C = (CSEL == 0) ? Cout : (float*)g_x;
    const int tid = threadIdx.x, wid = tid >> 5, lane = tid & 31;
    const int wm = wid & 3, wn = wid >> 2;    // 4 x 2 warps, warp tile 32 x 64
    const int bm = blockIdx.x * 128, nb = blockIdx.y * 128;
    const uint32_t sb = smem_u32(sm);

    const int a_row = wm * 32 + (lane & 7) + ((lane >> 3) & 1) * 8;
    const int a_c   = (lane >> 4) & 1;
    const int b_row = wn * 64 + (lane & 7) + ((lane >> 4) & 1) * 8;
    const int b_c   = (lane >> 3) & 1;

    float acc[2][8][4];
#pragma unroll
    for (int mt = 0; mt < 2; mt++)
#pragma unroll
        for (int nt = 0; nt < 8; nt++)
#pragma unroll
            for (int i = 0; i < 4; i++) acc[mt][nt][i] = 0.f;

    auto load_stage = [&](int kc, int s) {
        uint32_t base = sb + s * STG_SZ;
#pragma unroll
        for (int i = 0; i < 4; i++) {
            int idx = tid + i * 256;
            int r = idx >> 3, cc = idx & 7;
            int grow = bm + r;
            int ok = (grow < M);
            int grc = ok ? grow : (M - 1);
            const __nv_bfloat16* src = (cc < 4)
                ? &g_ahi[(size_t)grc * K + kc * 32 + cc * 8]
                : &g_alo[(size_t)grc * K + kc * 32 + (cc - 4) * 8];
            uint32_t dst = base + (r << 7) + ((cc ^ (r & 7)) << 4);
            CP16(dst, src, ok ? 16 : 0);
        }
#pragma unroll
        for (int i = 0; i < 4; i++) {
            int idx = tid + i * 256;
            int r = idx >> 3, cc = idx & 7;
            const __nv_bfloat16* src = (cc < 4)
                ? &g_wthi[(size_t)(nb + r) * K + kc * 32 + cc * 8]
                : &g_wtlo[(size_t)(nb + r) * K + kc * 32 + (cc - 4) * 8];
            uint32_t dst = base + OB + (r << 7) + ((cc ^ (r & 7)) << 4);
            CP16(dst, src, 16);
        }
    };

    load_stage(0, 0);
    CP_COMMIT();

    const int NKC = K / 32;
    for (int kc = 0; kc < NKC; kc++) {
        int s = kc & 1;
        if (kc + 1 < NKC) {
            load_stage(kc + 1, s ^ 1);
            CP_COMMIT();
            CP_WAIT(1);
        } else {
            CP_WAIT(0);
        }
        __syncthreads();

        uint32_t stg = sb + s * STG_SZ;
#pragma unroll
        for (int ks = 0; ks < 2; ks++) {
            uint32_t ah[2][4], al[2][4], bh[4][4], bl[4][4];
            int ach = ks * 2 + a_c;
            int bch = ks * 2 + b_c;
#pragma unroll
            for (int mt = 0; mt < 2; mt++) {
                int row = a_row + mt * 16;
                uint32_t rb_ = stg + (row << 7);
                LDSM4(ah[mt], rb_ + ((ach ^ (row & 7)) << 4));
                LDSM4(al[mt], rb_ + (((ach + 4) ^ (row & 7)) << 4));
            }
#pragma unroll
            for (int p = 0; p < 4; p++) {
                int row = b_row + p * 16;
                uint32_t rb_ = stg + OB + (row << 7);
                LDSM4(bh[p], rb_ + ((bch ^ (row & 7)) << 4));
                LDSM4(bl[p], rb_ + (((bch + 4) ^ (row & 7)) << 4));
            }
#pragma unroll
            for (int mt = 0; mt < 2; mt++)
#pragma unroll
                for (int nt = 0; nt < 8; nt++) {
                    int p = nt >> 1, s2 = (nt & 1) * 2;
                    MMA_BF16(acc[mt][nt], ah[mt], bh[p][s2], bh[p][s2 + 1]);
                    MMA_BF16(acc[mt][nt], ah[mt], bl[p][s2], bl[p][s2 + 1]);
                    MMA_BF16(acc[mt][nt], al[mt], bh[p][s2], bh[p][s2 + 1]);
                }
        }
        __syncthreads();
    }

    // ---- epilogue: + bias, relu, store fp32 ----
#pragma unroll
    for (int mt = 0; mt < 2; mt++) {
        int r0 = bm + wm * 32 + mt * 16 + (lane >> 2);
        int r1 = r0 + 8;
#pragma unroll
        for (int nt = 0; nt < 8; nt++) {
            int col = nb + wn * 64 + nt * 8 + (lane & 3) * 2;
            float bb0 = bias[col], bb1 = bias[col + 1];
            if (r0 < M) {
                float2 v = make_float2(fmaxf(acc[mt][nt][0] + bb0, 0.f),
                                       fmaxf(acc[mt][nt][1] + bb1, 0.f));
                *(float2*)&C[(size_t)r0 * Nn + col] = v;
            }
            if (r1 < M) {
                float2 v = make_float2(fmaxf(acc[mt][nt][2] + bb0, 0.f),
                                       fmaxf(acc[mt][nt][3] + bb1, 0.f));
                *(float2*)&C[(size_t)r1 * Nn + col] = v;
            }
        }
    }
}

// ================= pooling =================
__global__ void k_gate(const float* __restrict__ pw, const float* __restrict__ pb) {
    int warp = (blockIdx.x * blockDim.x + threadIdx.x) >> 5;
    int lane = threadIdx.x & 31;
    if (warp >= NNODES) return;
    const float* row = &g_x[(size_t)warp * 512];
    float s = 0.f;
#pragma unroll 4
    for (int i = lane; i < 512; i += 32) s += row[i] * pw[i];
#pragma unroll
    for (int o = 16; o; o >>= 1) s += __shfl_xor_sync(0xFFFFFFFFu, s, o);
    if (lane == 0) g_wgate[warp] = 1.f / (1.f + expf(-(s + pb[0])));
}

__global__ void k_gstart(const int* __restrict__ batch) {
    for (int n = blockIdx.x * blockDim.x + threadIdx.x; n < NNODES;
         n += gridDim.x * blockDim.x) {
        int b = batch[n];
        if (b < 0) b = 0;
        if (b >= NGRAPH) b = NGRAPH - 1;
        int prev = -1;
        if (n) {
            prev = batch[n - 1];
            if (prev < 0) prev = 0;
            if (prev >= NGRAPH) prev = NGRAPH - 1;
        }
        for (int g = prev + 1; g <= b; g++) g_gstart[g] = n;
        if (n == NNODES - 1)
            for (int g = b + 1; g <= NGRAPH; g++) g_gstart[g] = NNODES;
    }
}

// pool writes the head GEMM A operand (bf16 hi/lo split, row g, K=1024)
__global__ void k_pool() {
    int g = blockIdx.x;
    int f = threadIdx.x;  // 256
    int s = g_gstart[g], e = g_gstart[g + 1];
    float ws0 = 0.f, ws1 = 0.f, mx0 = 0.f, mx1 = 0.f;
    for (int n = s; n < e; n++) {
        float w = g_wgate[n];
        float v0 = g_x[(size_t)n * 512 + f];
        float v1 = g_x[(size_t)n * 512 + f + 256];
        ws0 += v0 * w;
        ws1 += v1 * w;
        mx0 = fmaxf(mx0, v0);
        mx1 = fmaxf(mx1, v1);
    }
    size_t base = (size_t)g * 1024;
    float vs[4] = {ws0, ws1, mx0, mx1};
    int   cs[4] = {f, f + 256, 512 + f, 768 + f};
#pragma unroll
    for (int i = 0; i < 4; i++) {
        __nv_bfloat16 h = __float2bfloat16(vs[i]);
        g_ahi[base + cs[i]] = h;
        g_alo[base + cs[i]] = __float2bfloat16(vs[i] - __bfloat162float(h));
    }
}

extern "C" void kernel_launch(void* const* d_in, const int* in_sizes, int n_in,
                              void* d_out, int out_size) {
    const float* xin   = (const float*)d_in[0];
    const int*   ei    = (const int*)d_in[1];
    const int*   batch = (const int*)d_in[2];
    const float* W1 = (const float*)d_in[3];
    const float* b1 = (const float*)d_in[4];
    const float* W2 = (const float*)d_in[5];
    const float* b2 = (const float*)d_in[6];
    const float* W3 = (const float*)d_in[7];
    const float* b3 = (const float*)d_in[8];
    const float* pw = (const float*)d_in[9];
    const float* pb = (const float*)d_in[10];
    const float* Wo = (const float*)d_in[11];
    const float* bo = (const float*)d_in[12];
    float* out = (float*)d_out;

    cudaFuncSetAttribute(k_mmagemm<0>, cudaFuncAttributeMaxDynamicSharedMemorySize,
                         2 * STG_SZ);
    cudaFuncSetAttribute(k_mmagemm<1>, cudaFuncAttributeMaxDynamicSharedMemorySize,
                         2 * STG_SZ);

    // graph structure
    k_zero<<<196, 256>>>();
    k_deg<<<512, 256>>>(ei);
    k_dis<<<(NNODES + 255) / 256, 256>>>();
    k_scan1<<<4, 256>>>();
    k_scan2<<<1, 1024>>>();
    k_scan3<<<4, 256>>>();
    k_csr<<<512, 256>>>(ei);

    const int MBLK = (NNODES + 127) / 128;  // 391

    // layer 1
    k_aggpre<0><<<NNODES, 256>>>(xin);
    k_cvtwT<<<dim3(4, 4), 256>>>(W1, 256, KDIM);
    k_mmagemm<1><<<dim3(MBLK, 2), 256, 2 * STG_SZ>>>(nullptr, NNODES, 256, KDIM, b1);

    // layer 2
    k_aggpre<1><<<NNODES, 256>>>(nullptr);
    k_cvtwT<<<dim3(4, 4), 256>>>(W2, 256, KDIM);
    k_mmagemm<1><<<dim3(MBLK, 2), 256, 2 * STG_SZ>>>(nullptr, NNODES, 256, KDIM, b2);

    // layer 3
    k_aggpre<1><<<NNODES, 256>>>(nullptr);
    k_cvtwT<<<dim3(8, 4), 256>>>(W3, 512, KDIM);
    k_mmagemm<1><<<dim3(MBLK, 4), 256, 2 * STG_SZ>>>(nullptr, NNODES, 512, KDIM, b3);

    // pooling (k_pool emits head A operand split)
    k_gate<<<(NNODES + 7) / 8, 256>>>(pw, pb);
    k_gstart<<<196, 256>>>(batch);
    k_pool<<<NGRAPH, 256>>>();

    // head: [512,1024] @ [1024,2048] + bias, relu -> out
    k_cvtwT<<<dim3(32, 16), 256>>>(Wo, 2048, 1024);
    k_mmagemm<0><<<dim3(4, 16), 256, 2 * STG_SZ>>>(out, NGRAPH, 2048, 1024, bo);
}